// round 4
// baseline (speedup 1.0000x reference)
#include <cuda_runtime.h>
#include <cuda_bf16.h>
#include <stdint.h>
#include <math.h>

#define NB 4096
#define NP 4096
#define NF 1024
#define SHRINK 0.25f
#define LR 0.1f
#define EPS 1e-8f
#define WD 1e-2f
#define STEPS 50

#if defined(__CUDA_ARCH_FEAT_SM103_ALL) || defined(__CUDA_ARCH_FEAT_SM100_ALL) || \
    defined(__CUDA_ARCH_FEAT_SM101_ALL) || defined(__CUDA_ARCH_FEAT_SM120_ALL)
#define TC_OK 1
#else
#define TC_OK 0
#endif

// ---------------- persistent device state ----------------------------------
__device__ float g_u[(size_t)NB * NF];
__device__ float g_m[(size_t)NB * NF];
__device__ float g_v[(size_t)NB * NF];
__device__ float g_excite[(size_t)NB * NF];
__device__ float g_act[(size_t)NB * NF];
__device__ __nv_bfloat16 g_acth[2][(size_t)NB * NF];   // ping-pong (race fix)
__device__ __nv_bfloat16 g_actl[2][(size_t)NB * NF];
__device__ __nv_bfloat16 g_imgh[(size_t)NB * NP];
__device__ __nv_bfloat16 g_imgl[(size_t)NB * NP];
__device__ __nv_bfloat16 g_phih[(size_t)NP * NF];
__device__ __nv_bfloat16 g_phil[(size_t)NP * NF];
__device__ __nv_bfloat16 g_phith[(size_t)NF * NP];
__device__ __nv_bfloat16 g_phitl[(size_t)NF * NP];
__device__ __nv_bfloat16 g_Gh[(size_t)NF * NF];
__device__ __nv_bfloat16 g_Gl[(size_t)NF * NF];

// ---------------- PTX helpers ----------------------------------------------
__device__ __forceinline__ uint32_t smem_u32(const void* p) {
    uint32_t a;
    asm("{ .reg .u64 t; cvta.to.shared.u64 t, %1; cvt.u32.u64 %0, t; }"
        : "=r"(a) : "l"(p));
    return a;
}
__device__ __forceinline__ uint32_t elect_one() {
    uint32_t p;
    asm volatile("{\n\t.reg .pred p;\n\telect.sync _|p, 0xFFFFFFFF;\n\t"
                 "selp.b32 %0, 1, 0, p;\n\t}" : "=r"(p));
    return p;
}
__device__ __forceinline__ void cp_async16(uint32_t dst, const void* src) {
    asm volatile("cp.async.cg.shared.global [%0], [%1], 16;\n" :: "r"(dst), "l"(src));
}
__device__ __forceinline__ void cp_commit() {
    asm volatile("cp.async.commit_group;\n" ::: "memory");
}
__device__ __forceinline__ uint64_t mkdesc(uint32_t addr) {
    return ((uint64_t)2 << 61) | ((uint64_t)1 << 46) | ((uint64_t)64 << 32) |
           ((uint64_t)1 << 16) | ((uint64_t)(addr >> 4) & 0x3FFF);
}
__device__ __forceinline__ void mma_bf16_ss(uint32_t d_tmem, uint64_t a_desc,
                                            uint64_t b_desc, uint32_t idesc, bool acc) {
    uint32_t en = acc ? 1u : 0u;
    asm volatile(
        "{\n\t.reg .pred p;\n\tsetp.ne.u32 p, %5, 0;\n\t"
        "tcgen05.mma.cta_group::1.kind::f16 [%0], %1, %2, %3, {%4,%4,%4,%4}, p;\n\t}"
        :: "r"(d_tmem), "l"(a_desc), "l"(b_desc), "r"(idesc), "r"(0u), "r"(en)
        : "memory");
}
__device__ __forceinline__ void mbar_init(uint32_t a, uint32_t cnt) {
    asm volatile("mbarrier.init.shared.b64 [%0], %1;" :: "r"(a), "r"(cnt) : "memory");
}
__device__ __forceinline__ void mbar_wait(uint32_t a, uint32_t phase) {
    asm volatile(
        "{\n\t.reg .pred P;\n\tLW%=:\n\t"
        "mbarrier.try_wait.parity.shared.b64 P, [%0], %1;\n\t"
        "@!P bra LW%=;\n\t}" :: "r"(a), "r"(phase) : "memory");
}
__device__ __forceinline__ void tc_commit(uint32_t mbar) {
    asm volatile(
        "tcgen05.commit.cta_group::1.mbarrier::arrive::one.shared::cluster.b64 [%0];"
        :: "r"(mbar) : "memory");
}
__device__ __forceinline__ void ldtm32(uint32_t (&r)[32], uint32_t a) {
    asm volatile(
        "tcgen05.ld.sync.aligned.32x32b.x32.b32 "
        "{%0,%1,%2,%3,%4,%5,%6,%7,%8,%9,%10,%11,%12,%13,%14,%15,"
        "%16,%17,%18,%19,%20,%21,%22,%23,%24,%25,%26,%27,%28,%29,%30,%31}, [%32];"
        : "=r"(r[0]), "=r"(r[1]), "=r"(r[2]), "=r"(r[3]), "=r"(r[4]), "=r"(r[5]),
          "=r"(r[6]), "=r"(r[7]), "=r"(r[8]), "=r"(r[9]), "=r"(r[10]), "=r"(r[11]),
          "=r"(r[12]), "=r"(r[13]), "=r"(r[14]), "=r"(r[15]), "=r"(r[16]),
          "=r"(r[17]), "=r"(r[18]), "=r"(r[19]), "=r"(r[20]), "=r"(r[21]),
          "=r"(r[22]), "=r"(r[23]), "=r"(r[24]), "=r"(r[25]), "=r"(r[26]),
          "=r"(r[27]), "=r"(r[28]), "=r"(r[29]), "=r"(r[30]), "=r"(r[31])
        : "r"(a));
}

#define SM_BUF 1024

// Load NR-row x 64-col bf16 tile (128B/row), SW128 swizzled, via cp.async.
template <int NR>
__device__ __forceinline__ void load_tile(uint32_t dst, const __nv_bfloat16* src,
                                          int row0, int ld, int k0, int tid) {
    const char* base = (const char*)(src + (size_t)row0 * ld + k0);
    const size_t ldb = (size_t)ld * 2;
#pragma unroll
    for (int i = 0; i < NR * 8 / 128; i++) {
        int cg = tid + i * 128;
        int r = cg >> 3, c = cg & 7;
        uint32_t off = (uint32_t)(r * 128 + c * 16);
        uint32_t sw = off ^ ((off >> 3) & 0x70);
        cp_async16(dst + sw, base + (size_t)r * ldb + c * 16);
    }
}

struct GP {
    const __nv_bfloat16 *Ah, *Al, *Bh, *Bl;
    int ldA, ldB, kIters;
    float* outF; int ldc;             // EPI 0
    float c1, c2; int writeAct;       // EPI 2
    __nv_bfloat16 *aWh, *aWl;         // EPI 2 ping-pong write targets
    float* actF;                      // EPI 2 final fp32 act
};

// EPI: 0 = fp32 store, 1 = G (-I, bf16 split out), 2 = AdamW step
// BN:  N-tile (128 or 256). M-tile fixed at 128, K-chunk 64.
template <int EPI, int BN>
__global__ __launch_bounds__(128) void mma_gemm(GP P) {
#if TC_OK
    constexpr int BNB = BN * 128;              // bytes per B split tile
    constexpr int STG = 2 * 16384 + 2 * BNB;   // stage bytes
    constexpr uint32_t IDESC = 0x490u | ((uint32_t)(BN / 8) << 17) | (8u << 24);

    extern __shared__ char smem[];
    const uint32_t sb = smem_u32(smem);
    const int tid = threadIdx.x;
    const int wid = tid >> 5;
    const int m0 = blockIdx.y * 128, n0 = blockIdx.x * BN;

    if (wid == 0)
        asm volatile("tcgen05.alloc.cta_group::1.sync.aligned.shared::cta.b32 [%0], %1;"
                     :: "r"(sb + 0), "r"((uint32_t)BN) : "memory");
    if (tid < 2) mbar_init(sb + 8 + tid * 8, 1);   // per-stage MMA-done mbars
    __syncthreads();
    uint32_t tbase;
    asm volatile("ld.shared.b32 %0, [%1];" : "=r"(tbase) : "r"(sb + 0));

    // prologue: chunk 0 -> stage 0
    {
        uint32_t s0 = sb + SM_BUF;
        load_tile<128>(s0, P.Ah, m0, P.ldA, 0, tid);
        load_tile<128>(s0 + 16384, P.Al, m0, P.ldA, 0, tid);
        load_tile<BN>(s0 + 32768, P.Bh, n0, P.ldB, 0, tid);
        load_tile<BN>(s0 + 32768 + BNB, P.Bl, n0, P.ldB, 0, tid);
        cp_commit();
    }

    for (int k = 0; k < P.kIters; k++) {
        const int cur = k & 1, nxt = cur ^ 1;
        if (k + 1 < P.kIters) {
            // buffer nxt was consumed by MMA of iteration k-1 -> wait its commit
            if (k >= 1) mbar_wait(sb + 8 + nxt * 8, ((k - 1) >> 1) & 1);
            uint32_t sn = sb + SM_BUF + nxt * STG;
            int k0 = (k + 1) * 64;
            load_tile<128>(sn, P.Ah, m0, P.ldA, k0, tid);
            load_tile<128>(sn + 16384, P.Al, m0, P.ldA, k0, tid);
            load_tile<BN>(sn + 32768, P.Bh, n0, P.ldB, k0, tid);
            load_tile<BN>(sn + 32768 + BNB, P.Bl, n0, P.ldB, k0, tid);
            cp_commit();
            asm volatile("cp.async.wait_group 1;\n" ::: "memory");
        } else {
            asm volatile("cp.async.wait_group 0;\n" ::: "memory");
        }
        __syncthreads();
        asm volatile("fence.proxy.async.shared::cta;" ::: "memory");

        if (wid == 0 && elect_one()) {
            uint32_t sc = sb + SM_BUF + cur * STG;
            uint64_t ah = mkdesc(sc);
            uint64_t al = mkdesc(sc + 16384);
            uint64_t bh = mkdesc(sc + 32768);
            uint64_t bl = mkdesc(sc + 32768 + BNB);
            bool first = (k == 0);
#pragma unroll
            for (int ks = 0; ks < 4; ks++)
                mma_bf16_ss(tbase, ah + ks * 2, bh + ks * 2, IDESC, !(first && ks == 0));
#pragma unroll
            for (int ks = 0; ks < 4; ks++)
                mma_bf16_ss(tbase, ah + ks * 2, bl + ks * 2, IDESC, true);
#pragma unroll
            for (int ks = 0; ks < 4; ks++)
                mma_bf16_ss(tbase, al + ks * 2, bh + ks * 2, IDESC, true);
            tc_commit(sb + 8 + cur * 8);
        }
    }

    // wait for the last commit (tensor ops complete in order)
    {
        int L = P.kIters - 1;
        mbar_wait(sb + 8 + (L & 1) * 8, (L >> 1) & 1);
    }
    asm volatile("tcgen05.fence::after_thread_sync;" ::: "memory");

    const int row = m0 + tid;
#pragma unroll
    for (int q = 0; q < BN / 32; q++) {
        uint32_t d[32];
        ldtm32(d, tbase + q * 32);
        asm volatile("tcgen05.wait::ld.sync.aligned;" ::: "memory");
        const int cbase = n0 + q * 32;

        if constexpr (EPI == 0) {
            float4* o = (float4*)(P.outF + (size_t)row * P.ldc + cbase);
#pragma unroll
            for (int jj = 0; jj < 8; jj++) {
                float4 v;
                v.x = __uint_as_float(d[jj * 4 + 0]);
                v.y = __uint_as_float(d[jj * 4 + 1]);
                v.z = __uint_as_float(d[jj * 4 + 2]);
                v.w = __uint_as_float(d[jj * 4 + 3]);
                o[jj] = v;
            }
        } else if constexpr (EPI == 1) {
#pragma unroll
            for (int j = 0; j < 32; j++) {
                float val = __uint_as_float(d[j]);
                if (row == cbase + j) val -= 1.0f;
                __nv_bfloat16 h = __float2bfloat16(val);
                __nv_bfloat16 l = __float2bfloat16(val - __bfloat162float(h));
                size_t idx = (size_t)row * NF + cbase + j;
                g_Gh[idx] = h;
                g_Gl[idx] = l;
            }
        } else {
            const size_t base = (size_t)row * NF + cbase;
#pragma unroll
            for (int jj = 0; jj < 8; jj++) {
                float4 uo = *(const float4*)(g_u + base + jj * 4);
                float4 mo = *(const float4*)(g_m + base + jj * 4);
                float4 vo = *(const float4*)(g_v + base + jj * 4);
                float4 ex = *(const float4*)(g_excite + base + jj * 4);
                float uoa[4] = {uo.x, uo.y, uo.z, uo.w};
                float moa[4] = {mo.x, mo.y, mo.z, mo.w};
                float voa[4] = {vo.x, vo.y, vo.z, vo.w};
                float exa[4] = {ex.x, ex.y, ex.z, ex.w};
                float4 mn4, vn4, un4;
                float* mnp = &mn4.x; float* vnp = &vn4.x; float* unp = &un4.x;
                float ac[4];
#pragma unroll
                for (int c = 0; c < 4; c++) {
                    float s = __uint_as_float(d[jj * 4 + c]);
                    float g = uoa[c] - exa[c] + s;
                    float mn = 0.9f * moa[c] + 0.1f * g;
                    float vn = 0.999f * voa[c] + 0.001f * g * g;
                    float u2 = uoa[c] * (1.0f - LR * WD);
                    u2 -= LR * (mn * P.c1) / (sqrtf(vn * P.c2) + EPS);
                    mnp[c] = mn; vnp[c] = vn; unp[c] = u2;
                    ac[c] = fmaxf(u2 - SHRINK, 0.0f);
                }
                *(float4*)(g_u + base + jj * 4) = un4;
                *(float4*)(g_m + base + jj * 4) = mn4;
                *(float4*)(g_v + base + jj * 4) = vn4;
#pragma unroll
                for (int c = 0; c < 4; c++) {
                    __nv_bfloat16 h = __float2bfloat16(ac[c]);
                    __nv_bfloat16 l = __float2bfloat16(ac[c] - __bfloat162float(h));
                    P.aWh[base + jj * 4 + c] = h;
                    P.aWl[base + jj * 4 + c] = l;
                }
                if (P.writeAct) {
                    float4 a4; a4.x = ac[0]; a4.y = ac[1]; a4.z = ac[2]; a4.w = ac[3];
                    *(float4*)(P.actF + base + jj * 4) = a4;
                }
            }
        }
    }

    asm volatile("tcgen05.fence::before_thread_sync;" ::: "memory");
    __syncthreads();
    if (wid == 0)
        asm volatile("tcgen05.dealloc.cta_group::1.sync.aligned.b32 %0, %1;"
                     :: "r"(tbase), "r"((uint32_t)BN));
#else
    (void)P;
#endif
}

// ---------------- elementwise AdamW steps (act(t-1) provably == 0) ----------
// |u1| < LR = 0.1, |u2| <= 0.0999*0.999 + 0.1*1.0013 < 0.2005 < SHRINK=0.25,
// so act1 == act2 == 0 exactly and steps 1..3 need no GEMM.
template <bool FIRST>
__global__ void k_step_ew(float c1, float c2, int writeActs,
                          __nv_bfloat16* __restrict__ awh,
                          __nv_bfloat16* __restrict__ awl) {
    size_t i4 = (size_t)blockIdx.x * blockDim.x + threadIdx.x;
    if (i4 >= (size_t)NB * NF / 4) return;
    float4 ex = ((const float4*)g_excite)[i4];
    float4 uo, mo, vo;
    if (FIRST) {
        uo = make_float4(0.f, 0.f, 0.f, 0.f);
        mo = uo; vo = uo;
    } else {
        uo = ((const float4*)g_u)[i4];
        mo = ((const float4*)g_m)[i4];
        vo = ((const float4*)g_v)[i4];
    }
    float uoa[4] = {uo.x, uo.y, uo.z, uo.w};
    float moa[4] = {mo.x, mo.y, mo.z, mo.w};
    float voa[4] = {vo.x, vo.y, vo.z, vo.w};
    float exa[4] = {ex.x, ex.y, ex.z, ex.w};
    float4 mn4, vn4, un4;
    float* mnp = &mn4.x; float* vnp = &vn4.x; float* unp = &un4.x;
#pragma unroll
    for (int c = 0; c < 4; c++) {
        float g = uoa[c] - exa[c];      // S = act@G = 0
        float mn = 0.9f * moa[c] + 0.1f * g;
        float vn = 0.999f * voa[c] + 0.001f * g * g;
        float u2 = uoa[c] * (1.0f - LR * WD);
        u2 -= LR * (mn * c1) / (sqrtf(vn * c2) + EPS);
        mnp[c] = mn; vnp[c] = vn; unp[c] = u2;
    }
    ((float4*)g_u)[i4] = un4;
    ((float4*)g_m)[i4] = mn4;
    ((float4*)g_v)[i4] = vn4;
    if (writeActs) {
        size_t b = i4 * 4;
#pragma unroll
        for (int c = 0; c < 4; c++) {
            float ac = fmaxf(unp[c] - SHRINK, 0.0f);
            __nv_bfloat16 h = __float2bfloat16(ac);
            awh[b + c] = h;
            awl[b + c] = __float2bfloat16(ac - __bfloat162float(h));
        }
    }
}

// ---------------- converts ---------------------------------------------------
__global__ void k_conv_img(const float* __restrict__ img) {
    size_t i = (size_t)blockIdx.x * blockDim.x + threadIdx.x;
    if (i < (size_t)NB * NP) {
        float x = img[i];
        __nv_bfloat16 h = __float2bfloat16(x);
        g_imgh[i] = h;
        g_imgl[i] = __float2bfloat16(x - __bfloat162float(h));
    }
}

// tiled transpose convert: filters [NP, NF] -> phih/l (same layout) + phith/l (T)
__global__ void k_conv_phi(const float* __restrict__ f) {
    __shared__ float tile[32][33];
    int c0 = blockIdx.x * 32, p0 = blockIdx.y * 32;
    int tx = threadIdx.x, ty = threadIdx.y;
#pragma unroll
    for (int i = ty; i < 32; i += 8) {
        float x = f[(size_t)(p0 + i) * NF + c0 + tx];
        tile[i][tx] = x;
        __nv_bfloat16 h = __float2bfloat16(x);
        size_t idx = (size_t)(p0 + i) * NF + c0 + tx;
        g_phih[idx] = h;
        g_phil[idx] = __float2bfloat16(x - __bfloat162float(h));
    }
    __syncthreads();
#pragma unroll
    for (int i = ty; i < 32; i += 8) {
        float x = tile[tx][i];   // element [p0+tx][c0+i]
        __nv_bfloat16 h = __float2bfloat16(x);
        size_t idx = (size_t)(c0 + i) * NP + p0 + tx;   // coalesced in tx
        g_phith[idx] = h;
        g_phitl[idx] = __float2bfloat16(x - __bfloat162float(h));
    }
}

// ---------------- launcher ---------------------------------------------------
extern "C" void kernel_launch(void* const* d_in, const int* in_sizes, int n_in,
                              void* d_out, int out_size) {
    const float* images  = (const float*)d_in[0];
    const float* filters = (const float*)d_in[1];
    if (in_sizes[0] == NP * NF && in_sizes[1] == NB * NP) {
        filters = (const float*)d_in[0];
        images  = (const float*)d_in[1];
    }
    float* out = (float*)d_out;

    constexpr int SMEM_128 = SM_BUF + 2 * (2 * 16384 + 2 * 128 * 128);  // 132 KB
    constexpr int SMEM_256 = SM_BUF + 2 * (2 * 16384 + 2 * 256 * 128);  // 197 KB
    cudaFuncSetAttribute(mma_gemm<1, 128>, cudaFuncAttributeMaxDynamicSharedMemorySize, SMEM_128);
    cudaFuncSetAttribute(mma_gemm<0, 256>, cudaFuncAttributeMaxDynamicSharedMemorySize, SMEM_256);
    cudaFuncSetAttribute(mma_gemm<2, 256>, cudaFuncAttributeMaxDynamicSharedMemorySize, SMEM_256);

    const __nv_bfloat16 *imgh, *imgl, *phih, *phil, *phith, *phitl, *Gh, *Gl;
    __nv_bfloat16 *acth0, *actl0, *acth1, *actl1;
    float *act, *excite;
    cudaGetSymbolAddress((void**)&imgh, g_imgh);
    cudaGetSymbolAddress((void**)&imgl, g_imgl);
    cudaGetSymbolAddress((void**)&phih, g_phih);
    cudaGetSymbolAddress((void**)&phil, g_phil);
    cudaGetSymbolAddress((void**)&phith, g_phith);
    cudaGetSymbolAddress((void**)&phitl, g_phitl);
    cudaGetSymbolAddress((void**)&Gh, g_Gh);
    cudaGetSymbolAddress((void**)&Gl, g_Gl);
    cudaGetSymbolAddress((void**)&acth0, g_acth);
    cudaGetSymbolAddress((void**)&actl0, g_actl);
    acth1 = acth0 + (size_t)NB * NF;
    actl1 = actl0 + (size_t)NB * NF;
    cudaGetSymbolAddress((void**)&act, g_act);
    cudaGetSymbolAddress((void**)&excite, g_excite);
    __nv_bfloat16* ah[2] = {acth0, acth1};
    __nv_bfloat16* al[2] = {actl0, actl1};

    // converts
    {
        size_t n = (size_t)NB * NP;
        k_conv_img<<<(unsigned)((n + 255) / 256), 256>>>(images);
    }
    k_conv_phi<<<dim3(NF / 32, NP / 32), dim3(32, 8)>>>(filters);

    // G = Phi^T Phi - I  (BN=128: grid 8x8, parallelism-limited)
    {
        GP p{};
        p.Ah = phith; p.Al = phitl; p.Bh = phith; p.Bl = phitl;
        p.ldA = NP; p.ldB = NP; p.kIters = NP / 64;
        mma_gemm<1, 128><<<dim3(NF / 128, NF / 128), 128, SMEM_128>>>(p);
    }

    // excite = images @ Phi
    {
        GP p{};
        p.Ah = imgh; p.Al = imgl; p.Bh = phith; p.Bl = phitl;
        p.ldA = NP; p.ldB = NP; p.kIters = NP / 64;
        p.outF = excite; p.ldc = NF;
        mma_gemm<0, 256><<<dim3(NF / 256, NB / 128), 128, SMEM_256>>>(p);
    }

    // steps 1..3: act(t-1) == 0 provably -> elementwise AdamW, no GEMM, no init
    double b1t = 1.0, b2t = 1.0;
    unsigned ewg = (unsigned)(((size_t)NB * NF / 4 + 255) / 256);
    for (int t = 1; t <= 3; t++) {
        b1t *= 0.9; b2t *= 0.999;
        float c1 = (float)(1.0 / (1.0 - b1t));
        float c2 = (float)(1.0 / (1.0 - b2t));
        int wA = (t == 3) ? 1 : 0;
        if (t == 1) k_step_ew<true><<<ewg, 256>>>(c1, c2, wA, ah[t & 1], al[t & 1]);
        else        k_step_ew<false><<<ewg, 256>>>(c1, c2, wA, ah[t & 1], al[t & 1]);
    }

    // steps 4..50: GEMM + fused AdamW epilogue, ping-pong act buffers
    for (int t = 4; t <= STEPS; t++) {
        b1t *= 0.9; b2t *= 0.999;
        GP sp{};
        sp.Ah = ah[(t - 1) & 1]; sp.Al = al[(t - 1) & 1];
        sp.Bh = Gh; sp.Bl = Gl;
        sp.ldA = NF; sp.ldB = NF; sp.kIters = NF / 64;
        sp.c1 = (float)(1.0 / (1.0 - b1t));
        sp.c2 = (float)(1.0 / (1.0 - b2t));
        sp.writeAct = (t == STEPS) ? 1 : 0;
        sp.aWh = ah[t & 1]; sp.aWl = al[t & 1];
        sp.actF = act;
        mma_gemm<2, 256><<<dim3(NF / 256, NB / 128), 128, SMEM_256>>>(sp);
    }

    // recon = act @ Phi^T -> d_out
    {
        GP p{};
        p.Ah = ah[STEPS & 1]; p.Al = al[STEPS & 1];
        p.Bh = phih; p.Bl = phil;
        p.ldA = NF; p.ldB = NF; p.kIters = NF / 64;
        p.outF = out; p.ldc = NP;
        mma_gemm<0, 256><<<dim3(NP / 256, NB / 128), 128, SMEM_256>>>(p);
    }

    cudaMemcpyAsync(out + (size_t)NB * NP, act,
                    (size_t)NB * NF * sizeof(float), cudaMemcpyDeviceToDevice);
}

// round 5
// speedup vs baseline: 1.6391x; 1.6391x over previous
#include <cuda_runtime.h>
#include <cuda_bf16.h>
#include <stdint.h>
#include <math.h>

#define NB 4096
#define NP 4096
#define NF 1024
#define SHRINK 0.25f
#define LR 0.1f
#define EPS 1e-8f
#define WD 1e-2f
#define STEPS 50

#if defined(__CUDA_ARCH_FEAT_SM103_ALL) || defined(__CUDA_ARCH_FEAT_SM100_ALL) || \
    defined(__CUDA_ARCH_FEAT_SM101_ALL) || defined(__CUDA_ARCH_FEAT_SM120_ALL)
#define TC_OK 1
#else
#define TC_OK 0
#endif

#define NTHR 256

// ---------------- persistent device state ----------------------------------
__device__ float g_u[(size_t)NB * NF];
__device__ float g_m[(size_t)NB * NF];
__device__ float g_v[(size_t)NB * NF];
__device__ float g_excite[(size_t)NB * NF];
__device__ float g_act[(size_t)NB * NF];
__device__ __nv_bfloat16 g_acth[2][(size_t)NB * NF];
__device__ __nv_bfloat16 g_actl[2][(size_t)NB * NF];
__device__ __nv_bfloat16 g_imgh[(size_t)NB * NP];
__device__ __nv_bfloat16 g_imgl[(size_t)NB * NP];
__device__ __nv_bfloat16 g_phih[(size_t)NP * NF];
__device__ __nv_bfloat16 g_phil[(size_t)NP * NF];
__device__ __nv_bfloat16 g_phith[(size_t)NF * NP];
__device__ __nv_bfloat16 g_phitl[(size_t)NF * NP];
__device__ __nv_bfloat16 g_Gh[(size_t)NF * NF];
__device__ __nv_bfloat16 g_Gl[(size_t)NF * NF];

// ---------------- PTX helpers ----------------------------------------------
__device__ __forceinline__ uint32_t smem_u32(const void* p) {
    uint32_t a;
    asm("{ .reg .u64 t; cvta.to.shared.u64 t, %1; cvt.u32.u64 %0, t; }"
        : "=r"(a) : "l"(p));
    return a;
}
__device__ __forceinline__ uint32_t elect_one() {
    uint32_t p;
    asm volatile("{\n\t.reg .pred p;\n\telect.sync _|p, 0xFFFFFFFF;\n\t"
                 "selp.b32 %0, 1, 0, p;\n\t}" : "=r"(p));
    return p;
}
__device__ __forceinline__ void cp_async16(uint32_t dst, const void* src) {
    asm volatile("cp.async.cg.shared.global [%0], [%1], 16;\n" :: "r"(dst), "l"(src));
}
__device__ __forceinline__ void cp_commit() {
    asm volatile("cp.async.commit_group;\n" ::: "memory");
}
__device__ __forceinline__ uint64_t mkdesc(uint32_t addr) {
    return ((uint64_t)2 << 61) | ((uint64_t)1 << 46) | ((uint64_t)64 << 32) |
           ((uint64_t)1 << 16) | ((uint64_t)(addr >> 4) & 0x3FFF);
}
__device__ __forceinline__ void mma_bf16_ss(uint32_t d_tmem, uint64_t a_desc,
                                            uint64_t b_desc, uint32_t idesc, bool acc) {
    uint32_t en = acc ? 1u : 0u;
    asm volatile(
        "{\n\t.reg .pred p;\n\tsetp.ne.u32 p, %5, 0;\n\t"
        "tcgen05.mma.cta_group::1.kind::f16 [%0], %1, %2, %3, {%4,%4,%4,%4}, p;\n\t}"
        :: "r"(d_tmem), "l"(a_desc), "l"(b_desc), "r"(idesc), "r"(0u), "r"(en)
        : "memory");
}
__device__ __forceinline__ void mbar_init(uint32_t a, uint32_t cnt) {
    asm volatile("mbarrier.init.shared.b64 [%0], %1;" :: "r"(a), "r"(cnt) : "memory");
}
__device__ __forceinline__ void mbar_wait(uint32_t a, uint32_t phase) {
    asm volatile(
        "{\n\t.reg .pred P;\n\tLW%=:\n\t"
        "mbarrier.try_wait.parity.shared.b64 P, [%0], %1;\n\t"
        "@!P bra LW%=;\n\t}" :: "r"(a), "r"(phase) : "memory");
}
__device__ __forceinline__ void tc_commit(uint32_t mbar) {
    asm volatile(
        "tcgen05.commit.cta_group::1.mbarrier::arrive::one.shared::cluster.b64 [%0];"
        :: "r"(mbar) : "memory");
}
__device__ __forceinline__ void ldtm32(uint32_t (&r)[32], uint32_t a) {
    asm volatile(
        "tcgen05.ld.sync.aligned.32x32b.x32.b32 "
        "{%0,%1,%2,%3,%4,%5,%6,%7,%8,%9,%10,%11,%12,%13,%14,%15,"
        "%16,%17,%18,%19,%20,%21,%22,%23,%24,%25,%26,%27,%28,%29,%30,%31}, [%32];"
        : "=r"(r[0]), "=r"(r[1]), "=r"(r[2]), "=r"(r[3]), "=r"(r[4]), "=r"(r[5]),
          "=r"(r[6]), "=r"(r[7]), "=r"(r[8]), "=r"(r[9]), "=r"(r[10]), "=r"(r[11]),
          "=r"(r[12]), "=r"(r[13]), "=r"(r[14]), "=r"(r[15]), "=r"(r[16]),
          "=r"(r[17]), "=r"(r[18]), "=r"(r[19]), "=r"(r[20]), "=r"(r[21]),
          "=r"(r[22]), "=r"(r[23]), "=r"(r[24]), "=r"(r[25]), "=r"(r[26]),
          "=r"(r[27]), "=r"(r[28]), "=r"(r[29]), "=r"(r[30]), "=r"(r[31])
        : "r"(a));
}

#define SM_BUF 1024

// Load NR-row x 64-col bf16 tile (128B/row), SW128 swizzled. NTHR threads.
template <int NR>
__device__ __forceinline__ void load_tile(uint32_t dst, const __nv_bfloat16* src,
                                          int row0, int ld, int k0, int tid) {
    const char* base = (const char*)(src + (size_t)row0 * ld + k0);
    const size_t ldb = (size_t)ld * 2;
#pragma unroll
    for (int i = 0; i < NR * 8 / NTHR; i++) {
        int cg = tid + i * NTHR;
        int r = cg >> 3, c = cg & 7;
        uint32_t off = (uint32_t)(r * 128 + c * 16);
        uint32_t sw = off ^ ((off >> 3) & 0x70);
        cp_async16(dst + sw, base + (size_t)r * ldb + c * 16);
    }
}

struct GP {
    const __nv_bfloat16 *Ah, *Al, *Bh, *Bl;
    int ldA, ldB, kIters;
    float* outF; int ldc;             // EPI 0
    float c1, c2; int writeAct;       // EPI 2
    __nv_bfloat16 *aWh, *aWl;         // EPI 2 ping-pong write targets
    float* actF;                      // EPI 2 final fp32 act
};

// EPI: 0 = fp32 store, 1 = G (-I, bf16 split out), 2 = AdamW step
template <int EPI, int BN>
__global__ __launch_bounds__(NTHR) void mma_gemm(GP P) {
#if TC_OK
    constexpr int BNB = BN * 128;
    constexpr int STG = 2 * 16384 + 2 * BNB;
    constexpr uint32_t IDESC = 0x490u | ((uint32_t)(BN / 8) << 17) | (8u << 24);
    constexpr int QTOT = BN / 32;       // 32-col blocks
    constexpr int QHALF = QTOT / 2;     // per warpgroup

    extern __shared__ char smem[];
    const uint32_t sb = smem_u32(smem);
    const int tid = threadIdx.x;
    const int wid = tid >> 5;
    const int m0 = blockIdx.y * 128, n0 = blockIdx.x * BN;

    if (wid == 0)
        asm volatile("tcgen05.alloc.cta_group::1.sync.aligned.shared::cta.b32 [%0], %1;"
                     :: "r"(sb + 0), "r"((uint32_t)BN) : "memory");
    if (tid < 2) mbar_init(sb + 8 + tid * 8, 1);
    __syncthreads();
    uint32_t tbase;
    asm volatile("ld.shared.b32 %0, [%1];" : "=r"(tbase) : "r"(sb + 0));

    // prologue: chunk 0 -> stage 0
    {
        uint32_t s0 = sb + SM_BUF;
        load_tile<128>(s0, P.Ah, m0, P.ldA, 0, tid);
        load_tile<128>(s0 + 16384, P.Al, m0, P.ldA, 0, tid);
        load_tile<BN>(s0 + 32768, P.Bh, n0, P.ldB, 0, tid);
        load_tile<BN>(s0 + 32768 + BNB, P.Bl, n0, P.ldB, 0, tid);
        cp_commit();
    }

    for (int k = 0; k < P.kIters; k++) {
        const int cur = k & 1, nxt = cur ^ 1;
        if (k + 1 < P.kIters) {
            if (k >= 1) mbar_wait(sb + 8 + nxt * 8, ((k - 1) >> 1) & 1);
            uint32_t sn = sb + SM_BUF + nxt * STG;
            int k0 = (k + 1) * 64;
            load_tile<128>(sn, P.Ah, m0, P.ldA, k0, tid);
            load_tile<128>(sn + 16384, P.Al, m0, P.ldA, k0, tid);
            load_tile<BN>(sn + 32768, P.Bh, n0, P.ldB, k0, tid);
            load_tile<BN>(sn + 32768 + BNB, P.Bl, n0, P.ldB, k0, tid);
            cp_commit();
            asm volatile("cp.async.wait_group 1;\n" ::: "memory");
        } else {
            asm volatile("cp.async.wait_group 0;\n" ::: "memory");
        }
        __syncthreads();
        asm volatile("fence.proxy.async.shared::cta;" ::: "memory");

        if (wid == 0 && elect_one()) {
            uint32_t sc = sb + SM_BUF + cur * STG;
            uint64_t ah = mkdesc(sc);
            uint64_t al = mkdesc(sc + 16384);
            uint64_t bh = mkdesc(sc + 32768);
            uint64_t bl = mkdesc(sc + 32768 + BNB);
            bool first = (k == 0);
#pragma unroll
            for (int ks = 0; ks < 4; ks++)
                mma_bf16_ss(tbase, ah + ks * 2, bh + ks * 2, IDESC, !(first && ks == 0));
#pragma unroll
            for (int ks = 0; ks < 4; ks++)
                mma_bf16_ss(tbase, ah + ks * 2, bl + ks * 2, IDESC, true);
#pragma unroll
            for (int ks = 0; ks < 4; ks++)
                mma_bf16_ss(tbase, al + ks * 2, bh + ks * 2, IDESC, true);
            tc_commit(sb + 8 + cur * 8);
        }
    }

    {
        int L = P.kIters - 1;
        mbar_wait(sb + 8 + (L & 1) * 8, (L >> 1) & 1);
    }
    asm volatile("tcgen05.fence::after_thread_sync;" ::: "memory");

    // Epilogue: 8 warps. Warp w reads TMEM subpartition (w%4) -> rows
    // m0 + (w%4)*32 + lane. Warpgroup (w/4) takes half the q-blocks.
    const int sub = wid & 3;
    const int wg = wid >> 2;
    const int lane = tid & 31;
    const int row = m0 + sub * 32 + lane;

#pragma unroll
    for (int qi = 0; qi < QHALF; qi++) {
        const int q = wg * QHALF + qi;
        uint32_t d[32];
        ldtm32(d, tbase + q * 32);
        asm volatile("tcgen05.wait::ld.sync.aligned;" ::: "memory");
        const int cbase = n0 + q * 32;

        if constexpr (EPI == 0) {
            float4* o = (float4*)(P.outF + (size_t)row * P.ldc + cbase);
#pragma unroll
            for (int jj = 0; jj < 8; jj++) {
                float4 v;
                v.x = __uint_as_float(d[jj * 4 + 0]);
                v.y = __uint_as_float(d[jj * 4 + 1]);
                v.z = __uint_as_float(d[jj * 4 + 2]);
                v.w = __uint_as_float(d[jj * 4 + 3]);
                o[jj] = v;
            }
        } else if constexpr (EPI == 1) {
#pragma unroll
            for (int j = 0; j < 32; j++) {
                float val = __uint_as_float(d[j]);
                if (row == cbase + j) val -= 1.0f;
                __nv_bfloat16 h = __float2bfloat16(val);
                __nv_bfloat16 l = __float2bfloat16(val - __bfloat162float(h));
                size_t idx = (size_t)row * NF + cbase + j;
                g_Gh[idx] = h;
                g_Gl[idx] = l;
            }
        } else {
            const size_t base = (size_t)row * NF + cbase;
            // two half-blocks of 4 jj each: batch 16 independent float4 loads
#pragma unroll
            for (int h2 = 0; h2 < 2; h2++) {
                float4 uo[4], mo[4], vo[4], ex[4];
#pragma unroll
                for (int j = 0; j < 4; j++) {
                    int jj = h2 * 4 + j;
                    uo[j] = *(const float4*)(g_u + base + jj * 4);
                    mo[j] = *(const float4*)(g_m + base + jj * 4);
                    vo[j] = *(const float4*)(g_v + base + jj * 4);
                    ex[j] = *(const float4*)(g_excite + base + jj * 4);
                }
#pragma unroll
                for (int j = 0; j < 4; j++) {
                    int jj = h2 * 4 + j;
                    float uoa[4] = {uo[j].x, uo[j].y, uo[j].z, uo[j].w};
                    float moa[4] = {mo[j].x, mo[j].y, mo[j].z, mo[j].w};
                    float voa[4] = {vo[j].x, vo[j].y, vo[j].z, vo[j].w};
                    float exa[4] = {ex[j].x, ex[j].y, ex[j].z, ex[j].w};
                    float4 mn4, vn4, un4;
                    float* mnp = &mn4.x; float* vnp = &vn4.x; float* unp = &un4.x;
                    float ac[4];
#pragma unroll
                    for (int c = 0; c < 4; c++) {
                        float s = __uint_as_float(d[jj * 4 + c]);
                        float g = uoa[c] - exa[c] + s;
                        float mn = 0.9f * moa[c] + 0.1f * g;
                        float vn = 0.999f * voa[c] + 0.001f * g * g;
                        float u2 = uoa[c] * (1.0f - LR * WD);
                        u2 -= LR * (mn * P.c1) / (sqrtf(vn * P.c2) + EPS);
                        mnp[c] = mn; vnp[c] = vn; unp[c] = u2;
                        ac[c] = fmaxf(u2 - SHRINK, 0.0f);
                    }
                    *(float4*)(g_u + base + jj * 4) = un4;
                    *(float4*)(g_m + base + jj * 4) = mn4;
                    *(float4*)(g_v + base + jj * 4) = vn4;
                    // pack 4 bf16 h and 4 bf16 l as single 8B stores
                    __nv_bfloat162 hh0, hh1, ll0, ll1;
                    hh0.x = __float2bfloat16(ac[0]); hh0.y = __float2bfloat16(ac[1]);
                    hh1.x = __float2bfloat16(ac[2]); hh1.y = __float2bfloat16(ac[3]);
                    ll0.x = __float2bfloat16(ac[0] - __bfloat162float(hh0.x));
                    ll0.y = __float2bfloat16(ac[1] - __bfloat162float(hh0.y));
                    ll1.x = __float2bfloat16(ac[2] - __bfloat162float(hh1.x));
                    ll1.y = __float2bfloat16(ac[3] - __bfloat162float(hh1.y));
                    *(__nv_bfloat162*)(P.aWh + base + jj * 4) = hh0;
                    *(__nv_bfloat162*)(P.aWh + base + jj * 4 + 2) = hh1;
                    *(__nv_bfloat162*)(P.aWl + base + jj * 4) = ll0;
                    *(__nv_bfloat162*)(P.aWl + base + jj * 4 + 2) = ll1;
                    if (P.writeAct) {
                        float4 a4; a4.x = ac[0]; a4.y = ac[1]; a4.z = ac[2]; a4.w = ac[3];
                        *(float4*)(P.actF + base + jj * 4) = a4;
                    }
                }
            }
        }
    }

    asm volatile("tcgen05.fence::before_thread_sync;" ::: "memory");
    __syncthreads();
    if (wid == 0)
        asm volatile("tcgen05.dealloc.cta_group::1.sync.aligned.b32 %0, %1;"
                     :: "r"(tbase), "r"((uint32_t)BN));
#else
    (void)P;
#endif
}

// ---------------- fused elementwise AdamW steps 1..3 ------------------------
// With u0=m0=v0=0: |u1| < 0.1, |u2| < 0.2005 < SHRINK -> act1 = act2 = 0
// exactly, so S=0 for steps 1..3; the whole prefix is pointwise.
__global__ void k_step_ew3(float c11, float c21, float c12, float c22,
                           float c13, float c23,
                           __nv_bfloat16* __restrict__ awh,
                           __nv_bfloat16* __restrict__ awl) {
    size_t i4 = (size_t)blockIdx.x * blockDim.x + threadIdx.x;
    if (i4 >= (size_t)NB * NF / 4) return;
    float4 ex4 = ((const float4*)g_excite)[i4];
    float exa[4] = {ex4.x, ex4.y, ex4.z, ex4.w};
    float4 un4, mn4, vn4;
    float* unp = &un4.x; float* mnp = &mn4.x; float* vnp = &vn4.x;
    size_t b = i4 * 4;
#pragma unroll
    for (int c = 0; c < 4; c++) {
        float u = 0.f, m = 0.f, v = 0.f;
        float cc1[3] = {c11, c12, c13};
        float cc2[3] = {c21, c22, c23};
#pragma unroll
        for (int t = 0; t < 3; t++) {
            float g = u - exa[c];
            m = 0.9f * m + 0.1f * g;
            v = 0.999f * v + 0.001f * g * g;
            u = u * (1.0f - LR * WD);
            u -= LR * (m * cc1[t]) / (sqrtf(v * cc2[t]) + EPS);
        }
        unp[c] = u; mnp[c] = m; vnp[c] = v;
        float ac = fmaxf(u - SHRINK, 0.0f);
        __nv_bfloat16 h = __float2bfloat16(ac);
        awh[b + c] = h;
        awl[b + c] = __float2bfloat16(ac - __bfloat162float(h));
    }
    ((float4*)g_u)[i4] = un4;
    ((float4*)g_m)[i4] = mn4;
    ((float4*)g_v)[i4] = vn4;
}

// ---------------- converts ---------------------------------------------------
__global__ void k_conv_img(const float* __restrict__ img) {
    size_t i = (size_t)blockIdx.x * blockDim.x + threadIdx.x;
    if (i < (size_t)NB * NP) {
        float x = img[i];
        __nv_bfloat16 h = __float2bfloat16(x);
        g_imgh[i] = h;
        g_imgl[i] = __float2bfloat16(x - __bfloat162float(h));
    }
}

__global__ void k_conv_phi(const float* __restrict__ f) {
    __shared__ float tile[32][33];
    int c0 = blockIdx.x * 32, p0 = blockIdx.y * 32;
    int tx = threadIdx.x, ty = threadIdx.y;
#pragma unroll
    for (int i = ty; i < 32; i += 8) {
        float x = f[(size_t)(p0 + i) * NF + c0 + tx];
        tile[i][tx] = x;
        __nv_bfloat16 h = __float2bfloat16(x);
        size_t idx = (size_t)(p0 + i) * NF + c0 + tx;
        g_phih[idx] = h;
        g_phil[idx] = __float2bfloat16(x - __bfloat162float(h));
    }
    __syncthreads();
#pragma unroll
    for (int i = ty; i < 32; i += 8) {
        float x = tile[tx][i];
        __nv_bfloat16 h = __float2bfloat16(x);
        size_t idx = (size_t)(c0 + i) * NP + p0 + tx;
        g_phith[idx] = h;
        g_phitl[idx] = __float2bfloat16(x - __bfloat162float(h));
    }
}

// ---------------- launcher ---------------------------------------------------
extern "C" void kernel_launch(void* const* d_in, const int* in_sizes, int n_in,
                              void* d_out, int out_size) {
    const float* images  = (const float*)d_in[0];
    const float* filters = (const float*)d_in[1];
    if (in_sizes[0] == NP * NF && in_sizes[1] == NB * NP) {
        filters = (const float*)d_in[0];
        images  = (const float*)d_in[1];
    }
    float* out = (float*)d_out;

    constexpr int SMEM_128 = SM_BUF + 2 * (2 * 16384 + 2 * 128 * 128);
    constexpr int SMEM_256 = SM_BUF + 2 * (2 * 16384 + 2 * 256 * 128);
    cudaFuncSetAttribute(mma_gemm<1, 128>, cudaFuncAttributeMaxDynamicSharedMemorySize, SMEM_128);
    cudaFuncSetAttribute(mma_gemm<0, 256>, cudaFuncAttributeMaxDynamicSharedMemorySize, SMEM_256);
    cudaFuncSetAttribute(mma_gemm<2, 256>, cudaFuncAttributeMaxDynamicSharedMemorySize, SMEM_256);

    const __nv_bfloat16 *imgh, *imgl, *phih, *phil, *phith, *phitl, *Gh, *Gl;
    __nv_bfloat16 *acth0, *actl0;
    float *act, *excite;
    cudaGetSymbolAddress((void**)&imgh, g_imgh);
    cudaGetSymbolAddress((void**)&imgl, g_imgl);
    cudaGetSymbolAddress((void**)&phih, g_phih);
    cudaGetSymbolAddress((void**)&phil, g_phil);
    cudaGetSymbolAddress((void**)&phith, g_phith);
    cudaGetSymbolAddress((void**)&phitl, g_phitl);
    cudaGetSymbolAddress((void**)&Gh, g_Gh);
    cudaGetSymbolAddress((void**)&Gl, g_Gl);
    cudaGetSymbolAddress((void**)&acth0, g_acth);
    cudaGetSymbolAddress((void**)&actl0, g_actl);
    cudaGetSymbolAddress((void**)&act, g_act);
    cudaGetSymbolAddress((void**)&excite, g_excite);
    __nv_bfloat16* ah[2] = {acth0, acth0 + (size_t)NB * NF};
    __nv_bfloat16* al[2] = {actl0, actl0 + (size_t)NB * NF};

    {
        size_t n = (size_t)NB * NP;
        k_conv_img<<<(unsigned)((n + 255) / 256), 256>>>(images);
    }
    k_conv_phi<<<dim3(NF / 32, NP / 32), dim3(32, 8)>>>(filters);

    // G = Phi^T Phi - I
    {
        GP p{};
        p.Ah = phith; p.Al = phitl; p.Bh = phith; p.Bl = phitl;
        p.ldA = NP; p.ldB = NP; p.kIters = NP / 64;
        mma_gemm<1, 128><<<dim3(NF / 128, NF / 128), NTHR, SMEM_128>>>(p);
    }

    // excite = images @ Phi
    {
        GP p{};
        p.Ah = imgh; p.Al = imgl; p.Bh = phith; p.Bl = phitl;
        p.ldA = NP; p.ldB = NP; p.kIters = NP / 64;
        p.outF = excite; p.ldc = NF;
        mma_gemm<0, 256><<<dim3(NF / 256, NB / 128), NTHR, SMEM_256>>>(p);
    }

    // steps 1..3 fused elementwise
    double b1t = 1.0, b2t = 1.0;
    float c1s[3], c2s[3];
    for (int t = 0; t < 3; t++) {
        b1t *= 0.9; b2t *= 0.999;
        c1s[t] = (float)(1.0 / (1.0 - b1t));
        c2s[t] = (float)(1.0 / (1.0 - b2t));
    }
    {
        unsigned ewg = (unsigned)(((size_t)NB * NF / 4 + 255) / 256);
        k_step_ew3<<<ewg, 256>>>(c1s[0], c2s[0], c1s[1], c2s[1], c1s[2], c2s[2],
                                 ah[1], al[1]);   // t=3 -> buf 1
    }

    // steps 4..50: GEMM + fused AdamW epilogue
    for (int t = 4; t <= STEPS; t++) {
        b1t *= 0.9; b2t *= 0.999;
        GP sp{};
        sp.Ah = ah[(t - 1) & 1]; sp.Al = al[(t - 1) & 1];
        sp.Bh = Gh; sp.Bl = Gl;
        sp.ldA = NF; sp.ldB = NF; sp.kIters = NF / 64;
        sp.c1 = (float)(1.0 / (1.0 - b1t));
        sp.c2 = (float)(1.0 / (1.0 - b2t));
        sp.writeAct = (t == STEPS) ? 1 : 0;
        sp.aWh = ah[t & 1]; sp.aWl = al[t & 1];
        sp.actF = act;
        mma_gemm<2, 256><<<dim3(NF / 256, NB / 128), NTHR, SMEM_256>>>(sp);
    }

    // recon = act @ Phi^T -> d_out
    {
        GP p{};
        p.Ah = ah[STEPS & 1]; p.Al = al[STEPS & 1];
        p.Bh = phih; p.Bl = phil;
        p.ldA = NF; p.ldB = NF; p.kIters = NF / 64;
        p.outF = out; p.ldc = NP;
        mma_gemm<0, 256><<<dim3(NP / 256, NB / 128), NTHR, SMEM_256>>>(p);
    }

    cudaMemcpyAsync(out + (size_t)NB * NP, act,
                    (size_t)NB * NF * sizeof(float), cudaMemcpyDeviceToDevice);
}